// round 11
// baseline (speedup 1.0000x reference)
#include <cuda_runtime.h>
#include <cstddef>
#include <cstdint>

#define LAYERS 5
#define H 128
#define T 2048
#define BATCH 256
#define G 29            // batch groups per layer (grid = 145)
#define BG 9            // rows per group
#define BPAD 264        // padded batch rows in staging buffer
#define NTH 576         // 64 j-pairs x 9 rows
#define KCH 16          // k-rows per TMA chunk
#define NCHUNK 8        // chunks per step (128/16)
#define NBUF 3          // weight ring buffers
#define NWARP 18
#define CHUNK_BYTES (5 * KCH * H * 4)   // 40960
#define MAT_BYTES   (KCH * H * 4)       // 8192
#define PUB 8           // flag publish granularity

typedef unsigned long long ull;

__device__ float Xbuf[(size_t)(LAYERS - 1) * T * BPAD * H];
__device__ int progressFlag[LAYERS * G];

__device__ __forceinline__ ull pack2(float lo, float hi) {
    ull r; asm("mov.b64 %0,{%1,%2};" : "=l"(r) : "f"(lo), "f"(hi)); return r;
}
__device__ __forceinline__ void fma2(ull& acc, ull a, ull b) {
    asm("fma.rn.f32x2 %0,%1,%2,%0;" : "+l"(acc) : "l"(a), "l"(b));
}
__device__ __forceinline__ void unpk(ull v, float& lo, float& hi) {
    asm("mov.b64 {%0,%1},%2;" : "=f"(lo), "=f"(hi) : "l"(v));
}
__device__ __forceinline__ float lo_of(ull v) {
    return __uint_as_float((unsigned)(v & 0xffffffffull));
}
__device__ __forceinline__ float fast_sigmoid(float x) {
    return 1.0f / (1.0f + __expf(-x));
}
__device__ __forceinline__ int ld_acquire(const int* p) {
    int v; asm volatile("ld.acquire.gpu.s32 %0,[%1];" : "=r"(v) : "l"(p) : "memory"); return v;
}
__device__ __forceinline__ void st_release(int* p, int v) {
    asm volatile("st.release.gpu.s32 [%0],%1;" :: "l"(p), "r"(v) : "memory");
}
__device__ __forceinline__ uint32_t smem_u32(const void* p) {
    uint32_t a;
    asm("{ .reg .u64 t; cvta.to.shared.u64 t, %1; cvt.u32.u64 %0, t; }" : "=r"(a) : "l"(p));
    return a;
}
#define MBAR_INIT(a, n) \
    asm volatile("mbarrier.init.shared.b64 [%0], %1;" :: "r"(a), "r"(n) : "memory")
#define MBAR_EXPECT_TX(a, bytes) \
    asm volatile("mbarrier.arrive.expect_tx.shared.b64 _, [%0], %1;" :: "r"(a), "r"(bytes) : "memory")
#define MBAR_ARRIVE(a) \
    asm volatile("mbarrier.arrive.shared.b64 _, [%0];" :: "r"(a) : "memory")
#define TMA_BULK(dst, src, bytes, mbar) \
    asm volatile("cp.async.bulk.shared::cta.global.mbarrier::complete_tx::bytes [%0], [%1], %2, [%3];" \
                 :: "r"(dst), "l"(src), "r"(bytes), "r"(mbar) : "memory")
#define FENCE_ASYNC() asm volatile("fence.proxy.async.shared::cta;" ::: "memory")

__device__ __forceinline__ void mbar_wait(uint32_t mbar, uint32_t parity) {
    uint32_t done;
    asm volatile(
        "{\n\t.reg .pred p;\n\t"
        "mbarrier.try_wait.parity.acquire.cta.shared::cta.b64 p, [%1], %2;\n\t"
        "selp.b32 %0, 1, 0, p;\n\t}"
        : "=r"(done) : "r"(mbar), "r"(parity) : "memory");
    if (!done) {
        asm volatile(
            "{\n\t.reg .pred P1;\n\t"
            "W%=:\n\t"
            "mbarrier.try_wait.parity.acquire.cta.shared::cta.b64 P1, [%0], %1, 0x989680;\n\t"
            "@P1 bra.uni D%=;\n\t"
            "bra.uni W%=;\n\t"
            "D%=:\n\t}"
            :: "r"(mbar), "r"(parity) : "memory");
    }
}

struct Smem {
    float wbuf[NBUF][5][KCH][H];   // 122880 B  streamed stage-A weights
    float whh_s[H][H];             //  65536 B  resident W_hh
    ulonglong2 hx[BG][H];          //  18432 B  {h,h | x,x}
    ull   rh2[BG][H];              //   9216 B  (R*h replicated)
    float br[H]; float bz[H]; float bh_[H];   // 1536 B
    int   avail_sh;
    ull   mbar_full[NBUF];
    ull   mbar_empty[NBUF];
};                                 // ~218 KB

__global__ void reset_kernel() {
    int i = threadIdx.x;
    if (i < LAYERS * G) progressFlag[i] = 0;
}

__global__ __launch_bounds__(NTH, 1)
void gru_layer_kernel(
    const float* __restrict__ inp,
    const float* __restrict__ W_hr, const float* __restrict__ W_xr, const float* __restrict__ b_r,
    const float* __restrict__ W_hz, const float* __restrict__ W_xz, const float* __restrict__ b_z,
    const float* __restrict__ W_hh, const float* __restrict__ W_xh, const float* __restrict__ b_h,
    float* __restrict__ out)
{
    extern __shared__ char smem_raw[];
    Smem& sm = *reinterpret_cast<Smem*>(smem_raw);

    const int bid  = blockIdx.x;
    const int l    = bid / G;
    const int g    = bid % G;
    const int row0 = g * BG;
    const int tid  = threadIdx.x;
    const int lane = tid & 31;
    const int jp   = tid & 63;        // j-pair
    const int j0   = jp << 1;
    const int bs   = tid >> 6;        // my batch row 0..8
    const int row  = row0 + bs;

    const float* wsrc0 = W_hr + l * H * H;
    const float* wsrc1 = W_xr + l * H * H;
    const float* wsrc2 = W_hz + l * H * H;
    const float* wsrc3 = W_xz + l * H * H;
    const float* wsrc4 = W_xh + l * H * H;
    const float* whh_g = W_hh + l * H * H;

    // ---- init smem ----
    for (int i = tid; i < BG * H; i += NTH)
        reinterpret_cast<ulonglong2*>(&sm.hx[0][0])[i] = make_ulonglong2(0ull, 0ull);
    for (int i = tid; i < H; i += NTH) {
        sm.br[i]  = b_r[l * H + i];
        sm.bz[i]  = b_z[l * H + i];
        sm.bh_[i] = b_h[l * H + i];
    }
    // resident W_hh
    for (int i = tid; i < H * H / 4; i += NTH)
        reinterpret_cast<float4*>(&sm.whh_s[0][0])[i] =
            reinterpret_cast<const float4*>(whh_g)[i];

    uint32_t full_a[NBUF], empty_a[NBUF];
    #pragma unroll
    for (int i = 0; i < NBUF; ++i) {
        full_a[i]  = smem_u32(&sm.mbar_full[i]);
        empty_a[i] = smem_u32(&sm.mbar_empty[i]);
    }
    if (tid == 0) {
        #pragma unroll
        for (int i = 0; i < NBUF; ++i) {
            MBAR_INIT(full_a[i], 1);
            MBAR_INIT(empty_a[i], NWARP);
        }
    }
    __syncthreads();

    const uint32_t wbuf_a0 = smem_u32(&sm.wbuf[0][0][0][0]);
    const uint32_t hx_a    = smem_u32(&sm.hx[0][0]);
    const uint32_t rh_a    = smem_u32(&sm.rh2[0][0]);
    const uint32_t whh_a   = smem_u32(&sm.whh_s[0][0]);

    // tid0: prologue issues chunks 0,1,2
    int emptycnt[NBUF] = {0, 0, 0};
    if (tid == 0) {
        #pragma unroll
        for (int m = 0; m < NBUF; ++m) {
            const int src_c = m & (NCHUNK - 1);
            MBAR_EXPECT_TX(full_a[m], CHUNK_BYTES);
            const uint32_t d = wbuf_a0 + m * (5 * MAT_BYTES);
            TMA_BULK(d,                 wsrc0 + src_c * KCH * H, MAT_BYTES, full_a[m]);
            TMA_BULK(d + 1 * MAT_BYTES, wsrc1 + src_c * KCH * H, MAT_BYTES, full_a[m]);
            TMA_BULK(d + 2 * MAT_BYTES, wsrc2 + src_c * KCH * H, MAT_BYTES, full_a[m]);
            TMA_BULK(d + 3 * MAT_BYTES, wsrc3 + src_c * KCH * H, MAT_BYTES, full_a[m]);
            TMA_BULK(d + 4 * MAT_BYTES, wsrc4 + src_c * KCH * H, MAT_BYTES, full_a[m]);
        }
    }

    int fullcnt[NBUF] = {0, 0, 0};

    int avail = (l == 0) ? T : 0;
    const float* xsrc = (l == 0) ? nullptr : &Xbuf[(size_t)(l - 1) * T * BPAD * H];
    float* ysnk = (l == LAYERS - 1) ? nullptr : &Xbuf[(size_t)l * T * BPAD * H];
    int* myflag  = &progressFlag[l * G + g];
    int* srcflag = (l == 0) ? nullptr : &progressFlag[(l - 1) * G + g];

    const int TOTAL_CHUNKS = T * NCHUNK;
    int mglob = 0;                    // global chunk counter (all threads agree)
    int buf   = 0;                    // ring position

    for (int t = 0; t < T; ++t) {
        // ---- producer flag wait ----
        if (l > 0 && avail < t + 1) {
            if (tid == 0) {
                int v = ld_acquire(srcflag);
                while (v < t + 1) { __nanosleep(200); v = ld_acquire(srcflag); }
                sm.avail_sh = v;
            }
            __syncthreads();
            avail = sm.avail_sh;
        }

        // ---- xload: x_t -> hx .y ----
        #pragma unroll
        for (int u = 0; u < 2; ++u) {
            const int i = tid + u * NTH;
            const int b = i >> 7, k = i & 127;
            const int r = row0 + b;
            float v;
            if (l == 0) {
                v = (r < BATCH) ? inp[((size_t)r * T + t) * H + k] : 0.0f;
            } else {
                v = xsrc[((size_t)t * BPAD + r) * H + k];
            }
            sm.hx[b][k].y = pack2(v, v);
        }
        __syncthreads();

        // publish progress (combineB(t-1) complete for all threads here)
        if (l < LAYERS - 1 && tid == 0 && t > 0 && (t & (PUB - 1)) == 0) {
            __threadfence();
            st_release(myflag, t);
        }

        // ======== Stage A: full-k accumulation, chunk-streamed weights ========
        ull ar = 0ull, az = 0ull, ax = 0ull;
        #pragma unroll 1
        for (int c = 0; c < NCHUNK; ++c) {
            const int b = buf;
            mbar_wait(full_a[b], (uint32_t)(fullcnt[b] & 1));
            fullcnt[b]++;

            const uint32_t wb = wbuf_a0 + b * (5 * MAT_BYTES) + j0 * 4;
            const uint32_t hxrow = hx_a + (bs * H + c * KCH) * 16;
            #pragma unroll
            for (int kk = 0; kk < KCH; ++kk) {
                ull w1, w2, w3, w4, w5;
                const uint32_t wk = wb + kk * (H * 4);
                asm volatile("ld.shared.b64 %0,[%1];" : "=l"(w1) : "r"(wk));
                asm volatile("ld.shared.b64 %0,[%1];" : "=l"(w2) : "r"(wk + MAT_BYTES));
                asm volatile("ld.shared.b64 %0,[%1];" : "=l"(w3) : "r"(wk + 2 * MAT_BYTES));
                asm volatile("ld.shared.b64 %0,[%1];" : "=l"(w4) : "r"(wk + 3 * MAT_BYTES));
                asm volatile("ld.shared.b64 %0,[%1];" : "=l"(w5) : "r"(wk + 4 * MAT_BYTES));
                ull hh, xx;
                asm volatile("ld.shared.v2.u64 {%0,%1},[%2];"
                             : "=l"(hh), "=l"(xx) : "r"(hxrow + kk * 16));
                fma2(ar, w1, hh);
                fma2(ar, w2, xx);
                fma2(az, w3, hh);
                fma2(az, w4, xx);
                fma2(ax, w5, xx);
            }
            FENCE_ASYNC();
            __syncwarp();
            if (lane == 0) MBAR_ARRIVE(empty_a[b]);

            // tid0: refill this buffer with chunk mglob+NBUF
            if (tid == 0) {
                const int mn = mglob + NBUF;
                if (mn < TOTAL_CHUNKS) {
                    mbar_wait(empty_a[b], (uint32_t)(emptycnt[b] & 1));
                    emptycnt[b]++;
                    const int src_c = mn & (NCHUNK - 1);
                    MBAR_EXPECT_TX(full_a[b], CHUNK_BYTES);
                    const uint32_t d = wbuf_a0 + b * (5 * MAT_BYTES);
                    TMA_BULK(d,                 wsrc0 + src_c * KCH * H, MAT_BYTES, full_a[b]);
                    TMA_BULK(d + 1 * MAT_BYTES, wsrc1 + src_c * KCH * H, MAT_BYTES, full_a[b]);
                    TMA_BULK(d + 2 * MAT_BYTES, wsrc2 + src_c * KCH * H, MAT_BYTES, full_a[b]);
                    TMA_BULK(d + 3 * MAT_BYTES, wsrc3 + src_c * KCH * H, MAT_BYTES, full_a[b]);
                    TMA_BULK(d + 4 * MAT_BYTES, wsrc4 + src_c * KCH * H, MAT_BYTES, full_a[b]);
                }
            }
            mglob++;
            buf = (buf == NBUF - 1) ? 0 : buf + 1;
        }

        // ======== Combine A (register-local) ========
        float a0, a1, z0r, z1r, x0r, x1r;
        unpk(ar, a0, a1);
        unpk(az, z0r, z1r);
        unpk(ax, x0r, x1r);
        const float h0 = lo_of(sm.hx[bs][j0].x);
        const float h1 = lo_of(sm.hx[bs][j0 + 1].x);
        const float R0 = fast_sigmoid(a0 + sm.br[j0]);
        const float R1 = fast_sigmoid(a1 + sm.br[j0 + 1]);
        const float Z0 = fast_sigmoid(z0r + sm.bz[j0]);
        const float Z1 = fast_sigmoid(z1r + sm.bz[j0 + 1]);
        const float p0 = x0r + sm.bh_[j0];
        const float p1 = x1r + sm.bh_[j0 + 1];
        const float rv0 = R0 * h0;
        const float rv1 = R1 * h1;
        asm volatile("st.shared.b64 [%0],%1;" :: "r"(rh_a + (bs * H + j0) * 8), "l"(pack2(rv0, rv0)));
        asm volatile("st.shared.b64 [%0],%1;" :: "r"(rh_a + (bs * H + j0 + 1) * 8), "l"(pack2(rv1, rv1)));
        __syncthreads();

        // ======== Stage B: (R*h) @ W_hh from resident smem ========
        ull bh = 0ull;
        {
            const uint32_t wcol = whh_a + j0 * 4;
            const uint32_t rrow = rh_a + bs * H * 8;
            #pragma unroll 8
            for (int k = 0; k < H; ++k) {
                ull w, v;
                asm volatile("ld.shared.b64 %0,[%1];" : "=l"(w) : "r"(wcol + k * (H * 4)));
                asm volatile("ld.shared.b64 %0,[%1];" : "=l"(v) : "r"(rrow + k * 8));
                fma2(bh, w, v);
            }
        }

        // ======== Combine B (register-local) ========
        float s0, s1;
        unpk(bh, s0, s1);
        const float ht0 = tanhf(s0 + p0);
        const float ht1 = tanhf(s1 + p1);
        const float hn0 = Z0 * ht0 + (1.0f - Z0) * h0;
        const float hn1 = Z1 * ht1 + (1.0f - Z1) * h1;
        sm.hx[bs][j0].x     = pack2(hn0, hn0);
        sm.hx[bs][j0 + 1].x = pack2(hn1, hn1);
        if (l == LAYERS - 1) {
            if (row < BATCH)
                *reinterpret_cast<float2*>(&out[((size_t)row * T + t) * H + j0]) =
                    make_float2(hn0, hn1);
        } else {
            *reinterpret_cast<float2*>(&ysnk[((size_t)t * BPAD + row) * H + j0]) =
                make_float2(hn0, hn1);
        }
        // no trailing sync: next-iteration xload writes .y only; sync1 orders .x reads
    }

    __syncthreads();
    if (l < LAYERS - 1 && tid == 0) {
        __threadfence();
        st_release(myflag, T);
    }
}

extern "C" void kernel_launch(void* const* d_in, const int* in_sizes, int n_in,
                              void* d_out, int out_size) {
    (void)in_sizes; (void)n_in; (void)out_size;
    const float* inp  = (const float*)d_in[0];
    const float* W_hr = (const float*)d_in[1];
    const float* W_xr = (const float*)d_in[2];
    const float* b_r  = (const float*)d_in[3];
    const float* W_hz = (const float*)d_in[4];
    const float* W_xz = (const float*)d_in[5];
    const float* b_z  = (const float*)d_in[6];
    const float* W_hh = (const float*)d_in[7];
    const float* W_xh = (const float*)d_in[8];
    const float* b_h  = (const float*)d_in[9];
    float* out = (float*)d_out;

    reset_kernel<<<1, 256>>>();

    cudaFuncSetAttribute(gru_layer_kernel,
                         cudaFuncAttributeMaxDynamicSharedMemorySize,
                         (int)sizeof(Smem));
    gru_layer_kernel<<<LAYERS * G, NTH, sizeof(Smem)>>>(
        inp, W_hr, W_xr, b_r, W_hz, W_xz, b_z, W_hh, W_xh, b_h, out);
}

// round 14
// speedup vs baseline: 1.2472x; 1.2472x over previous
#include <cuda_runtime.h>
#include <cstddef>
#include <cstdint>

#define LAYERS 5
#define H 128
#define T 2048
#define BATCH 256
#define G 29            // batch groups per layer (grid = 145)
#define BG 9            // rows per group
#define BPAD 264        // padded batch rows in staging buffer
#define NTH 512
#define KS 8            // k-slices (one warp-pair per slice)
#define PUB 8           // flag publish granularity

#define NBUF_A 3
#define NBUF_B 2
#define ACH_K 8                          // k-rows per A chunk
#define ACH_PER_STEP 16
#define A_MAT_BYTES (ACH_K * H * 4)      // 4096
#define A_CHUNK_BYTES (5 * A_MAT_BYTES)  // 20480
#define BCH_K 16                         // k-rows per B chunk
#define BCH_PER_STEP 8
#define B_CHUNK_BYTES (BCH_K * H * 4)    // 8192

typedef unsigned long long ull;

__device__ float Xbuf[(size_t)(LAYERS - 1) * T * BPAD * H];
__device__ int progressFlag[LAYERS * G];

__device__ __forceinline__ ull pack2(float lo, float hi) {
    ull r; asm("mov.b64 %0,{%1,%2};" : "=l"(r) : "f"(lo), "f"(hi)); return r;
}
__device__ __forceinline__ void fma2(ull& acc, ull a, ull b) {
    asm("fma.rn.f32x2 %0,%1,%2,%0;" : "+l"(acc) : "l"(a), "l"(b));
}
__device__ __forceinline__ float lo_of(ull v) {
    return __uint_as_float((unsigned)(v & 0xffffffffull));
}
__device__ __forceinline__ float fast_sigmoid(float x) {
    return 1.0f / (1.0f + __expf(-x));
}
__device__ __forceinline__ int ld_acquire(const int* p) {
    int v; asm volatile("ld.acquire.gpu.s32 %0,[%1];" : "=r"(v) : "l"(p) : "memory"); return v;
}
__device__ __forceinline__ void st_release(int* p, int v) {
    asm volatile("st.release.gpu.s32 [%0],%1;" :: "l"(p), "r"(v) : "memory");
}
__device__ __forceinline__ uint32_t smem_u32(const void* p) {
    uint32_t a;
    asm("{ .reg .u64 t; cvta.to.shared.u64 t, %1; cvt.u32.u64 %0, t; }" : "=r"(a) : "l"(p));
    return a;
}
#define MBAR_INIT(a, n) \
    asm volatile("mbarrier.init.shared.b64 [%0], %1;" :: "r"(a), "r"(n) : "memory")
#define MBAR_EXPECT_TX(a, bytes) \
    asm volatile("mbarrier.arrive.expect_tx.shared.b64 _, [%0], %1;" :: "r"(a), "r"(bytes) : "memory")
#define MBAR_ARRIVE(a) \
    asm volatile("mbarrier.arrive.shared.b64 _, [%0];" :: "r"(a) : "memory")
#define TMA_BULK(dst, src, bytes, mbar) \
    asm volatile("cp.async.bulk.shared::cta.global.mbarrier::complete_tx::bytes [%0], [%1], %2, [%3];" \
                 :: "r"(dst), "l"(src), "r"(bytes), "r"(mbar) : "memory")

__device__ __forceinline__ void mbar_wait(uint32_t mbar, uint32_t parity) {
    uint32_t done;
    asm volatile(
        "{\n\t.reg .pred p;\n\t"
        "mbarrier.try_wait.parity.acquire.cta.shared::cta.b64 p, [%1], %2;\n\t"
        "selp.b32 %0, 1, 0, p;\n\t}"
        : "=r"(done) : "r"(mbar), "r"(parity) : "memory");
    if (!done) {
        asm volatile(
            "{\n\t.reg .pred P1;\n\t"
            "W%=:\n\t"
            "mbarrier.try_wait.parity.acquire.cta.shared::cta.b64 P1, [%0], %1, 0x989680;\n\t"
            "@P1 bra.uni D%=;\n\t"
            "bra.uni W%=;\n\t"
            "D%=:\n\t}"
            :: "r"(mbar), "r"(parity) : "memory");
    }
}

struct Smem {
    float wbufA[NBUF_A][5][ACH_K][H];   //  61440 B
    float wbufB[NBUF_B][BCH_K][H];      //  16384 B
    float partA[KS][3][BG][H];          // 110592 B (partB aliases this)
    ulonglong2 hx[BG][H];               //  18432 B  {h,h | x,x}
    ull   rh2[BG][H];                   //   9216 B
    float zbuf[BG][H];                  //   4608 B
    float preh[BG][H];                  //   4608 B
    float br[H]; float bz[H]; float bh_[H];  // 1536 B
    ull mbarAfP[ACH_PER_STEP];          // per-position full barriers (1 phase/step)
    ull mbarAe[NBUF_A];
    ull mbarBfP[BCH_PER_STEP];
    ull mbarBe[NBUF_B];
    int avail_sh;
};                                      // ~227 KB
static_assert(sizeof(Smem) <= 232448, "smem over limit");

__global__ void reset_kernel() {
    int i = threadIdx.x;
    if (i < LAYERS * G) progressFlag[i] = 0;
}

__global__ __launch_bounds__(NTH, 1)
void gru_layer_kernel(
    const float* __restrict__ inp,
    const float* __restrict__ W_hr, const float* __restrict__ W_xr, const float* __restrict__ b_r,
    const float* __restrict__ W_hz, const float* __restrict__ W_xz, const float* __restrict__ b_z,
    const float* __restrict__ W_hh, const float* __restrict__ W_xh, const float* __restrict__ b_h,
    float* __restrict__ out)
{
    extern __shared__ char smem_raw[];
    Smem& sm = *reinterpret_cast<Smem*>(smem_raw);
    float* partB = &sm.partA[0][0][0][0];      // [KS][BG][H] alias, disjoint lifetime

    const int bid  = blockIdx.x;
    const int l    = bid / G;
    const int g    = bid % G;
    const int row0 = g * BG;
    const int tid  = threadIdx.x;
    const int lane = tid & 31;
    const int jp   = tid & 63;
    const int j0   = jp << 1;
    const int ks   = (tid >> 6) & 7;

    const float* wA0 = W_hr + l * H * H;
    const float* wA1 = W_xr + l * H * H;
    const float* wA2 = W_hz + l * H * H;
    const float* wA3 = W_xz + l * H * H;
    const float* wA4 = W_xh + l * H * H;
    const float* whh = W_hh + l * H * H;

    for (int i = tid; i < BG * H; i += NTH) {
        reinterpret_cast<ulonglong2*>(&sm.hx[0][0])[i] = make_ulonglong2(0ull, 0ull);
        (&sm.rh2[0][0])[i] = 0ull;
    }
    for (int i = tid; i < H; i += NTH) {
        sm.br[i]  = b_r[l * H + i];
        sm.bz[i]  = b_z[l * H + i];
        sm.bh_[i] = b_h[l * H + i];
    }
    uint32_t AfP[ACH_PER_STEP], Ae[NBUF_A], BfP[BCH_PER_STEP], Be[NBUF_B];
    #pragma unroll
    for (int i = 0; i < ACH_PER_STEP; ++i) AfP[i] = smem_u32(&sm.mbarAfP[i]);
    #pragma unroll
    for (int i = 0; i < NBUF_A; ++i)       Ae[i]  = smem_u32(&sm.mbarAe[i]);
    #pragma unroll
    for (int i = 0; i < BCH_PER_STEP; ++i) BfP[i] = smem_u32(&sm.mbarBfP[i]);
    #pragma unroll
    for (int i = 0; i < NBUF_B; ++i)       Be[i]  = smem_u32(&sm.mbarBe[i]);
    if (tid == 0) {
        #pragma unroll
        for (int i = 0; i < ACH_PER_STEP; ++i) MBAR_INIT(AfP[i], 1);
        #pragma unroll
        for (int i = 0; i < NBUF_A; ++i)       MBAR_INIT(Ae[i], 2);
        #pragma unroll
        for (int i = 0; i < BCH_PER_STEP; ++i) MBAR_INIT(BfP[i], 1);
        #pragma unroll
        for (int i = 0; i < NBUF_B; ++i)       MBAR_INIT(Be[i], 2);
    }
    __syncthreads();

    const uint32_t wA_a = smem_u32(&sm.wbufA[0][0][0][0]);
    const uint32_t wB_a = smem_u32(&sm.wbufB[0][0][0]);

    int nextA = NBUF_A, nextB = NBUF_B;
    if (tid == 0) {
        // prologue: chunk n lands in buffer n%NBUF, signals AfP[n%16] (phase 0)
        #pragma unroll
        for (int m = 0; m < NBUF_A; ++m) {
            MBAR_EXPECT_TX(AfP[m], A_CHUNK_BYTES);
            const uint32_t d = wA_a + m * A_CHUNK_BYTES;
            TMA_BULK(d,                   wA0 + m * ACH_K * H, A_MAT_BYTES, AfP[m]);
            TMA_BULK(d + 1 * A_MAT_BYTES, wA1 + m * ACH_K * H, A_MAT_BYTES, AfP[m]);
            TMA_BULK(d + 2 * A_MAT_BYTES, wA2 + m * ACH_K * H, A_MAT_BYTES, AfP[m]);
            TMA_BULK(d + 3 * A_MAT_BYTES, wA3 + m * ACH_K * H, A_MAT_BYTES, AfP[m]);
            TMA_BULK(d + 4 * A_MAT_BYTES, wA4 + m * ACH_K * H, A_MAT_BYTES, AfP[m]);
        }
        #pragma unroll
        for (int m = 0; m < NBUF_B; ++m) {
            MBAR_EXPECT_TX(BfP[m], B_CHUNK_BYTES);
            TMA_BULK(wB_a + m * B_CHUNK_BYTES, whh + m * BCH_K * H, B_CHUNK_BYTES, BfP[m]);
        }
    }

    int avail = (l == 0) ? T : 0;
    const float* xsrc = (l == 0) ? nullptr : &Xbuf[(size_t)(l - 1) * T * BPAD * H];
    float* ysnk = (l == LAYERS - 1) ? nullptr : &Xbuf[(size_t)l * T * BPAD * H];
    int* myflag  = &progressFlag[l * G + g];
    int* srcflag = (l == 0) ? nullptr : &progressFlag[(l - 1) * G + g];

    for (int t = 0; t < T; ++t) {
        if (l > 0 && avail < t + 1) {
            if (tid == 0) {
                int v = ld_acquire(srcflag);
                while (v < t + 1) { __nanosleep(200); v = ld_acquire(srcflag); }
                sm.avail_sh = v;
            }
            __syncthreads();
            avail = sm.avail_sh;
        }

        for (int i = tid; i < BG * H; i += NTH) {
            const int b = i >> 7, k = i & 127;
            const int r = row0 + b;
            float v;
            if (l == 0) {
                v = (r < BATCH) ? inp[((size_t)r * T + t) * H + k] : 0.0f;
            } else {
                v = xsrc[((size_t)t * BPAD + r) * H + k];
            }
            sm.hx[b][k].y = pack2(v, v);
        }
        __syncthreads();

        if (l < LAYERS - 1 && tid == 0 && t > 0 && (t & (PUB - 1)) == 0) {
            __threadfence();
            st_release(myflag, t);
        }

        // ======== Stage A: my k-slice via 2 streamed chunks ========
        {
            ull ar[BG], az[BG], ax[BG];
            #pragma unroll
            for (int b = 0; b < BG; ++b) { ar[b] = 0ull; az[b] = 0ull; ax[b] = 0ull; }

            #pragma unroll
            for (int ci = 0; ci < 2; ++ci) {
                const int pos = 2 * ks + ci;               // fixed position per pair
                const int gA  = ACH_PER_STEP * t + pos;
                const int buf = gA % NBUF_A;
                mbar_wait(AfP[pos], (uint32_t)(t & 1));    // 1 phase per step: parity-safe

                #pragma unroll
                for (int kk = 0; kk < ACH_K; ++kk) {
                    const int k = ACH_K * pos + kk;
                    const ull w1 = *reinterpret_cast<const ull*>(&sm.wbufA[buf][0][kk][j0]);
                    const ull w2 = *reinterpret_cast<const ull*>(&sm.wbufA[buf][1][kk][j0]);
                    const ull w3 = *reinterpret_cast<const ull*>(&sm.wbufA[buf][2][kk][j0]);
                    const ull w4 = *reinterpret_cast<const ull*>(&sm.wbufA[buf][3][kk][j0]);
                    const ull w5 = *reinterpret_cast<const ull*>(&sm.wbufA[buf][4][kk][j0]);
                    #pragma unroll
                    for (int b = 0; b < BG; ++b) {
                        const ulonglong2 hxv = sm.hx[b][k];
                        fma2(ar[b], w1, hxv.x);
                        fma2(ar[b], w2, hxv.y);
                        fma2(az[b], w3, hxv.x);
                        fma2(az[b], w4, hxv.y);
                        fma2(ax[b], w5, hxv.y);
                    }
                }
                __syncwarp();
                if (lane == 0) MBAR_ARRIVE(Ae[buf]);
            }
            #pragma unroll
            for (int b = 0; b < BG; ++b) {
                *reinterpret_cast<ull*>(&sm.partA[ks][0][b][j0]) = ar[b];
                *reinterpret_cast<ull*>(&sm.partA[ks][1][b][j0]) = az[b];
                *reinterpret_cast<ull*>(&sm.partA[ks][2][b][j0]) = ax[b];
            }
        }

        // tid0 pump A: issue chunk n (buffer n%3) after release of chunk n-3
        if (tid == 0) {
            int hiA = ACH_PER_STEP * t + ACH_PER_STEP + 2;
            const int lastA = ACH_PER_STEP * T - 1;
            if (hiA > lastA) hiA = lastA;
            for (; nextA <= hiA; ++nextA) {
                const int buf = nextA % NBUF_A;
                const int pos = nextA % ACH_PER_STEP;
                mbar_wait(Ae[buf], (uint32_t)(((nextA / NBUF_A) - 1) & 1));
                MBAR_EXPECT_TX(AfP[pos], A_CHUNK_BYTES);
                const uint32_t d = wA_a + buf * A_CHUNK_BYTES;
                TMA_BULK(d,                   wA0 + pos * ACH_K * H, A_MAT_BYTES, AfP[pos]);
                TMA_BULK(d + 1 * A_MAT_BYTES, wA1 + pos * ACH_K * H, A_MAT_BYTES, AfP[pos]);
                TMA_BULK(d + 2 * A_MAT_BYTES, wA2 + pos * ACH_K * H, A_MAT_BYTES, AfP[pos]);
                TMA_BULK(d + 3 * A_MAT_BYTES, wA3 + pos * ACH_K * H, A_MAT_BYTES, AfP[pos]);
                TMA_BULK(d + 4 * A_MAT_BYTES, wA4 + pos * ACH_K * H, A_MAT_BYTES, AfP[pos]);
            }
        }
        __syncthreads();

        // ---- Combine A ----
        for (int i = tid; i < 3 * BG * H; i += NTH) {
            const int g3 = i / (BG * H);
            const int r  = i % (BG * H);
            const int b  = r >> 7;
            const int j  = r & 127;
            float ssum = 0.f;
            #pragma unroll
            for (int ss = 0; ss < KS; ++ss) ssum += sm.partA[ss][g3][b][j];
            if (g3 == 0) {
                const float R  = fast_sigmoid(ssum + sm.br[j]);
                const float rv = R * lo_of(sm.hx[b][j].x);
                sm.rh2[b][j] = pack2(rv, rv);
            } else if (g3 == 1) {
                sm.zbuf[b][j] = fast_sigmoid(ssum + sm.bz[j]);
            } else {
                sm.preh[b][j] = ssum + sm.bh_[j];
            }
        }
        __syncthreads();

        // ======== Stage B ========
        {
            const int pos = ks;
            const int gB  = BCH_PER_STEP * t + pos;
            const int buf = gB % NBUF_B;
            mbar_wait(BfP[pos], (uint32_t)(t & 1));

            ull bh[BG];
            #pragma unroll
            for (int b = 0; b < BG; ++b) bh[b] = 0ull;
            #pragma unroll 4
            for (int kk = 0; kk < BCH_K; ++kk) {
                const int k = BCH_K * pos + kk;
                const ull w = *reinterpret_cast<const ull*>(&sm.wbufB[buf][kk][j0]);
                #pragma unroll
                for (int b = 0; b < BG; ++b)
                    fma2(bh[b], w, sm.rh2[b][k]);
            }
            __syncwarp();
            if (lane == 0) MBAR_ARRIVE(Be[buf]);

            #pragma unroll
            for (int b = 0; b < BG; ++b)
                *reinterpret_cast<ull*>(&partB[((ks * BG + b) << 7) + j0]) = bh[b];
        }

        // tid0 pump B: issue chunk n (buffer n%2) after release of chunk n-2
        if (tid == 0) {
            int hiB = BCH_PER_STEP * t + BCH_PER_STEP + 1;
            const int lastB = BCH_PER_STEP * T - 1;
            if (hiB > lastB) hiB = lastB;
            for (; nextB <= hiB; ++nextB) {
                const int buf = nextB % NBUF_B;
                const int pos = nextB % BCH_PER_STEP;
                mbar_wait(Be[buf], (uint32_t)(((nextB / NBUF_B) - 1) & 1));
                MBAR_EXPECT_TX(BfP[pos], B_CHUNK_BYTES);
                TMA_BULK(wB_a + buf * B_CHUNK_BYTES, whh + pos * BCH_K * H, B_CHUNK_BYTES, BfP[pos]);
            }
        }
        __syncthreads();

        // ---- Combine B ----
        for (int i = tid; i < BG * H; i += NTH) {
            const int b = i >> 7;
            const int j = i & 127;
            float ssum = 0.f;
            #pragma unroll
            for (int ss = 0; ss < KS; ++ss) ssum += partB[((ss * BG + b) << 7) + j];
            const float htld = tanhf(ssum + sm.preh[b][j]);
            const float Z    = sm.zbuf[b][j];
            const float hv   = lo_of(sm.hx[b][j].x);
            const float hn   = Z * htld + (1.0f - Z) * hv;
            sm.hx[b][j].x = pack2(hn, hn);
            const int row = row0 + b;
            if (l == LAYERS - 1) {
                if (row < BATCH)
                    out[((size_t)row * T + t) * H + j] = hn;
            } else {
                ysnk[((size_t)t * BPAD + row) * H + j] = hn;
            }
        }
        __syncthreads();
    }

    if (l < LAYERS - 1 && tid == 0) {
        __threadfence();
        st_release(myflag, T);
    }
}

extern "C" void kernel_launch(void* const* d_in, const int* in_sizes, int n_in,
                              void* d_out, int out_size) {
    (void)in_sizes; (void)n_in; (void)out_size;
    const float* inp  = (const float*)d_in[0];
    const float* W_hr = (const float*)d_in[1];
    const float* W_xr = (const float*)d_in[2];
    const float* b_r  = (const float*)d_in[3];
    const float* W_hz = (const float*)d_in[4];
    const float* W_xz = (const float*)d_in[5];
    const float* b_z  = (const float*)d_in[6];
    const float* W_hh = (const float*)d_in[7];
    const float* W_xh = (const float*)d_in[8];
    const float* b_h  = (const float*)d_in[9];
    float* out = (float*)d_out;

    reset_kernel<<<1, 256>>>();

    cudaFuncSetAttribute(gru_layer_kernel,
                         cudaFuncAttributeMaxDynamicSharedMemorySize,
                         (int)sizeof(Smem));
    gru_layer_kernel<<<LAYERS * G, NTH, sizeof(Smem)>>>(
        inp, W_hr, W_xr, b_r, W_hz, W_xz, b_z, W_hh, W_xh, b_h, out);
}